// round 2
// baseline (speedup 1.0000x reference)
#include <cuda_runtime.h>

// Problem constants (fixed by setup_inputs)
#define T_   48
#define BS_  256
#define V_   4096
#define K_   32
#define U2_  64      // 2*K
#define RIDS_ 1024
#define EPSF 1e-9f

// Scratch (device globals — no allocation allowed)
__device__ float g_ptrue[T_ * BS_];     // per (t,b) dot(out_ids, tla)
__device__ float g_stepsum[T_ * BS_];   // per (t,b) sum of tla row
__device__ float g_distr[BS_ * V_];     // dist_r[b,v] = sum_t out_ids[t,b,v]
__device__ float g_acc_kl;              // sum over b of kl_b

// ---------------------------------------------------------------------------
// K0: zero the accumulated scratch (g_distr is fully overwritten, skip it)
// ---------------------------------------------------------------------------
__global__ void zero_kernel() {
    int i = blockIdx.x * blockDim.x + threadIdx.x;
    if (i < T_ * BS_) { g_ptrue[i] = 0.f; g_stepsum[i] = 0.f; }
    if (i == 0) g_acc_kl = 0.f;
}

// ---------------------------------------------------------------------------
// K1: big streaming pass over out_ids [T,BS,V] and trg_labels rows 1..T
//     grid: (V/1024, BS), 256 threads (8 warps), float4/thread, t unrolled x4.
//     Per-warp partials staged in smem; only 96 global atomics per block.
// ---------------------------------------------------------------------------
__global__ void __launch_bounds__(256) big_pass(
    const float* __restrict__ out_ids,
    const float* __restrict__ trg_labels)
{
    __shared__ float s_dot[T_][8];   // [t][warp]
    __shared__ float s_ls [T_][8];

    const int b    = blockIdx.y;
    const int v0   = blockIdx.x * 1024 + threadIdx.x * 4;
    const int lane = threadIdx.x & 31;
    const int warp = threadIdx.x >> 5;

    float4 dist = make_float4(0.f, 0.f, 0.f, 0.f);

    #pragma unroll 1
    for (int t0 = 0; t0 < T_; t0 += 4) {
        float4 o[4], l[4];
        // batch the loads to maximize MLP (8 LDG.128 in flight)
        #pragma unroll
        for (int j = 0; j < 4; j++) {
            int t = t0 + j;
            o[j] = *(const float4*)(out_ids    + ((t    ) * BS_ + b) * V_ + v0);
            l[j] = *(const float4*)(trg_labels + ((t + 1) * BS_ + b) * V_ + v0);
        }
        #pragma unroll
        for (int j = 0; j < 4; j++) {
            int t = t0 + j;
            dist.x += o[j].x; dist.y += o[j].y; dist.z += o[j].z; dist.w += o[j].w;
            float dot = o[j].x * l[j].x + o[j].y * l[j].y +
                        o[j].z * l[j].z + o[j].w * l[j].w;
            float ls  = l[j].x + l[j].y + l[j].z + l[j].w;
            #pragma unroll
            for (int off = 16; off > 0; off >>= 1) {
                dot += __shfl_down_sync(0xffffffffu, dot, off);
                ls  += __shfl_down_sync(0xffffffffu, ls,  off);
            }
            if (lane == 0) { s_dot[t][warp] = dot; s_ls[t][warp] = ls; }
        }
    }
    *(float4*)(g_distr + b * V_ + v0) = dist;

    __syncthreads();
    // 48 t-values x 2 quantities = 96 lanes of work; reduce 8 warp partials each
    for (int idx = threadIdx.x; idx < T_ * 2; idx += 256) {
        int t = idx >> 1;
        const float* src = (idx & 1) ? s_ls[t] : s_dot[t];
        float v = src[0] + src[1] + src[2] + src[3] +
                  src[4] + src[5] + src[6] + src[7];
        float* dst = (idx & 1) ? &g_stepsum[t * BS_ + b] : &g_ptrue[t * BS_ + b];
        atomicAdd(dst, v);
    }
}

// ---------------------------------------------------------------------------
// K2: per-batch KL over candidate unions. One CTA per b, 256 threads.
//     tbl[value] = first-occurrence slot index (or U2_ = invalid)
// ---------------------------------------------------------------------------
__global__ void __launch_bounds__(256) kl_kernel(
    const int*   __restrict__ candi_ids,
    const float* __restrict__ sel_probs,
    const int*   __restrict__ routes)
{
    __shared__ int   tbl[RIDS_];
    __shared__ int   ids_s[U2_];
    __shared__ float probs_s[U2_];
    __shared__ float Pm[U2_];
    __shared__ float agg[U2_];

    const int b = blockIdx.x, tid = threadIdx.x;

    for (int i = tid; i < RIDS_; i += 256) tbl[i] = U2_;
    if (tid < U2_) {
        ids_s[tid]   = candi_ids[b * U2_ + tid];
        probs_s[tid] = sel_probs[b * U2_ + tid];
        Pm[tid]  = 0.f;
        agg[tid] = 0.f;
    }
    __syncthreads();

    if (tid < U2_) atomicMin(&tbl[ids_s[tid]], tid);
    __syncthreads();

    if (tid < U2_) atomicAdd(&Pm[tbl[ids_s[tid]]], probs_s[tid]);
    __syncthreads();

    // project route mass onto union slots
    for (int v = tid; v < V_; v += 256) {
        int r = routes[b * V_ + v];
        int slot = tbl[r];
        if (slot < U2_) atomicAdd(&agg[slot], g_distr[b * V_ + v]);
    }
    __syncthreads();

    if (tid == 0) {
        float s = 0.f, PmSum = 0.f;
        int Ucnt = 0;
        #pragma unroll 4
        for (int u = 0; u < U2_; u++) {
            s += agg[u];
            PmSum += Pm[u];
            if (tbl[ids_s[u]] == u) Ucnt++;
        }
        const float invS  = 1.f / fmaxf(s, EPSF);
        const float uni   = 1.f / fmaxf((float)Ucnt, 1.f);
        const float invPm = 1.f / fmaxf(PmSum, EPSF);
        float kl = 0.f;
        for (int u = 0; u < U2_; u++) {
            if (tbl[ids_s[u]] != u) continue;      // invalid slot
            float Pb  = (s > 0.f) ? agg[u] * invS : uni;
            float Pbc = fmaxf(Pb, EPSF);
            float Pmn = fmaxf(Pm[u] * invPm, EPSF);
            kl += Pbc * (logf(Pbc) - logf(Pmn));
        }
        atomicAdd(&g_acc_kl, kl);
    }
}

// ---------------------------------------------------------------------------
// K3: epilogue — all small loss terms + final combine. One CTA, 1024 threads.
// ---------------------------------------------------------------------------
__global__ void __launch_bounds__(1024) final_kernel(
    const float* __restrict__ sel_probs,
    const float* __restrict__ sel_onehot,
    const float* __restrict__ out_rates,   // [T,BS]
    const float* __restrict__ trg_rates,   // [T+2,BS]
    const int*   __restrict__ trg_lengths, // [BS]
    float* __restrict__ d_out)
{
    const int tid = threadIdx.x;
    __shared__ float sacc[8];
    if (tid < 8) sacc[tid] = 0.f;
    __syncthreads();

    float sel_num = 0.f, sel_den = 0.f;
    float id_num = 0.f, id_den = 0.f;
    float rate_num = 0.f, ent = 0.f, smooth = 0.f, len_sum = 0.f;

    // selector NLL: 512 (b, j) pairs
    for (int idx = tid; idx < BS_ * 2; idx += 1024) {
        float pt = 0.f, ms = 0.f;
        const float* p  = sel_probs  + idx * K_;
        const float* oh = sel_onehot + idx * K_;
        #pragma unroll 8
        for (int k = 0; k < K_; k++) { pt += p[k] * oh[k]; ms += oh[k]; }
        float m = (ms > 0.5f) ? 1.f : 0.f;
        sel_num += -logf(fmaxf(pt, EPSF)) * m;
        sel_den += m;
    }

    // id NLL from precomputed per-(t,b) dots
    for (int idx = tid; idx < T_ * BS_; idx += 1024) {
        float m = (g_stepsum[idx] > 0.5f) ? 1.f : 0.f;
        id_num += -logf(fmaxf(g_ptrue[idx], EPSF)) * m;
        id_den += m;
    }

    // rate L1: |out_rates[t,b] - trg_rates[t+1,b]|
    for (int idx = tid; idx < T_ * BS_; idx += 1024) {
        int t = idx / BS_, b = idx % BS_;
        rate_num += fabsf(out_rates[idx] - trg_rates[(t + 1) * BS_ + b]);
    }

    // entropy of selector probs
    for (int idx = tid; idx < BS_ * 2 * K_; idx += 1024) {
        float p = fmaxf(sel_probs[idx], EPSF);
        ent += -p * logf(p);
    }

    // rate smoothness
    for (int idx = tid; idx < (T_ - 1) * BS_; idx += 1024) {
        int t = idx / BS_, b = idx % BS_;
        float dr = fabsf(out_rates[(t + 1) * BS_ + b] - out_rates[t * BS_ + b]);
        if (t < trg_lengths[b] - 3) smooth += dr;
    }

    // sum(trg_lengths - 2)
    for (int b = tid; b < BS_; b += 1024)
        len_sum += (float)(trg_lengths[b] - 2);

    // reduce all 8 partials: warp-reduce then shared atomic
    float vals[8] = {sel_num, sel_den, id_num, id_den, rate_num, ent, smooth, len_sum};
    #pragma unroll
    for (int i = 0; i < 8; i++) {
        float v = vals[i];
        #pragma unroll
        for (int off = 16; off > 0; off >>= 1)
            v += __shfl_down_sync(0xffffffffu, v, off);
        if ((tid & 31) == 0) atomicAdd(&sacc[i], v);
    }
    __syncthreads();

    if (tid == 0) {
        float loss_sel    = sacc[0] / fmaxf(sacc[1], 1.f);
        float loss_id     = 10.f * sacc[2] / fmaxf(sacc[3], 1.f);
        float loss_rate   = 5.f * sacc[4] / fmaxf(sacc[7], 1.f);
        float loss_kl     = 0.1f * g_acc_kl / (float)BS_;
        float loss_ent    = 0.05f * 0.5f * sacc[5] / (float)BS_;
        float loss_smooth = 0.5f * sacc[6];
        d_out[0] = loss_sel + loss_id + loss_rate + loss_kl + loss_ent + loss_smooth;
    }
}

// ---------------------------------------------------------------------------
extern "C" void kernel_launch(void* const* d_in, const int* in_sizes, int n_in,
                              void* d_out, int out_size) {
    // metadata order: selector_logits, selector_probs, selector_onehot,
    // out_ids, out_rates, trg_labels, trg_rates, trg_lengths, candi_ids, routes
    const float* sel_probs   = (const float*)d_in[1];
    const float* sel_onehot  = (const float*)d_in[2];
    const float* out_ids     = (const float*)d_in[3];
    const float* out_rates   = (const float*)d_in[4];
    const float* trg_labels  = (const float*)d_in[5];
    const float* trg_rates   = (const float*)d_in[6];
    const int*   trg_lengths = (const int*)d_in[7];
    const int*   candi_ids   = (const int*)d_in[8];
    const int*   routes      = (const int*)d_in[9];

    zero_kernel<<<12, 1024>>>();
    dim3 grid(V_ / 1024, BS_);
    big_pass<<<grid, 256>>>(out_ids, trg_labels);
    kl_kernel<<<BS_, 256>>>(candi_ids, sel_probs, routes);
    final_kernel<<<1, 1024>>>(sel_probs, sel_onehot, out_rates, trg_rates,
                              trg_lengths, (float*)d_out);
}

// round 7
// speedup vs baseline: 1.3068x; 1.3068x over previous
#include <cuda_runtime.h>

// Problem constants (fixed by setup_inputs)
#define T_   48
#define BS_  256
#define V_   4096
#define K_   32
#define U2_  64      // 2*K
#define RIDS_ 1024
#define NCHUNK 4     // V / 1024
#define TBATCH 6     // t-steps per load batch (12 LDG.128 in flight)
#define EPSF 1e-9f

// accumulator slots
#define A_SEL_NUM 0
#define A_SEL_DEN 1
#define A_ID_NUM  2
#define A_ID_DEN  3
#define A_RATE    4
#define A_ENT     5
#define A_SMOOTH  6
#define A_LEN     7
#define A_KL      8
#define NACC      9

// Scratch (device globals — no allocation allowed).
// All written exclusively per-block each call: no zeroing, no global atomics.
__device__ float g_ptrue4  [NCHUNK * T_ * BS_];  // per (chunk,t,b) partial dot
__device__ float g_stepsum4[NCHUNK * T_ * BS_];  // per (chunk,t,b) partial label-sum
__device__ float g_distr   [BS_ * V_];           // dist_r[b,v] = sum_t out_ids[t,b,v]
__device__ float g_part    [NACC * BS_];         // per-batch loss partials

// ---------------------------------------------------------------------------
// K1: big streaming pass over out_ids [T,BS,V] and trg_labels rows 1..T
//     grid: (NCHUNK, BS), 256 threads (8 warps), float4/thread, t batched x6.
//     Per-warp partials staged in smem; exclusive STG of chunk partials.
// ---------------------------------------------------------------------------
__global__ void __launch_bounds__(256) big_pass(
    const float* __restrict__ out_ids,
    const float* __restrict__ trg_labels)
{
    __shared__ float s_dot[T_][8];   // [t][warp]
    __shared__ float s_ls [T_][8];

    const int b    = blockIdx.y;
    const int v0   = blockIdx.x * 1024 + threadIdx.x * 4;
    const int lane = threadIdx.x & 31;
    const int warp = threadIdx.x >> 5;

    float4 dist = make_float4(0.f, 0.f, 0.f, 0.f);

    #pragma unroll 1
    for (int t0 = 0; t0 < T_; t0 += TBATCH) {
        float4 o[TBATCH], l[TBATCH];
        // batch the loads to maximize MLP (12 LDG.128 in flight)
        #pragma unroll
        for (int j = 0; j < TBATCH; j++) {
            int t = t0 + j;
            o[j] = *(const float4*)(out_ids    + ((t    ) * BS_ + b) * V_ + v0);
            l[j] = *(const float4*)(trg_labels + ((t + 1) * BS_ + b) * V_ + v0);
        }
        #pragma unroll
        for (int j = 0; j < TBATCH; j++) {
            int t = t0 + j;
            dist.x += o[j].x; dist.y += o[j].y; dist.z += o[j].z; dist.w += o[j].w;
            float dot = o[j].x * l[j].x + o[j].y * l[j].y +
                        o[j].z * l[j].z + o[j].w * l[j].w;
            float ls  = l[j].x + l[j].y + l[j].z + l[j].w;
            #pragma unroll
            for (int off = 16; off > 0; off >>= 1) {
                dot += __shfl_down_sync(0xffffffffu, dot, off);
                ls  += __shfl_down_sync(0xffffffffu, ls,  off);
            }
            if (lane == 0) { s_dot[t][warp] = dot; s_ls[t][warp] = ls; }
        }
    }
    *(float4*)(g_distr + b * V_ + v0) = dist;

    __syncthreads();
    // 48 t-values x 2 quantities = 96 writes; exclusive chunk slot, plain STG
    const int chunkOff = blockIdx.x * (T_ * BS_);
    for (int idx = threadIdx.x; idx < T_ * 2; idx += 256) {
        int t = idx >> 1;
        const float* src = (idx & 1) ? s_ls[t] : s_dot[t];
        float v = src[0] + src[1] + src[2] + src[3] +
                  src[4] + src[5] + src[6] + src[7];
        float* dst = (idx & 1) ? &g_stepsum4[chunkOff + t * BS_ + b]
                               : &g_ptrue4  [chunkOff + t * BS_ + b];
        *dst = v;
    }
}

// ---------------------------------------------------------------------------
// K2: per-batch KL + ALL per-batch epilogue terms. One CTA per b, 256 thr.
//     tbl[value] = first-occurrence slot index (or U2_ = invalid).
//     Writes 9 per-batch partials to g_part (exclusive, no atomics).
// ---------------------------------------------------------------------------
__global__ void __launch_bounds__(256) kl_epi_kernel(
    const int*   __restrict__ candi_ids,
    const float* __restrict__ sel_probs,
    const int*   __restrict__ routes,
    const float* __restrict__ sel_onehot,
    const float* __restrict__ out_rates,   // [T,BS]
    const float* __restrict__ trg_rates,   // [T+2,BS]
    const int*   __restrict__ trg_lengths) // [BS]
{
    __shared__ int   tbl[RIDS_];
    __shared__ int   ids_s[U2_];
    __shared__ float probs_s[U2_];
    __shared__ float Pm[U2_];
    __shared__ float agg[U2_];
    __shared__ float wpart[7][8];   // warp partials for 7 scalar terms

    const int b = blockIdx.x, tid = threadIdx.x;
    const int lane = tid & 31, warp = tid >> 5;

    for (int i = tid; i < RIDS_; i += 256) tbl[i] = U2_;
    if (tid < U2_) {
        ids_s[tid]   = candi_ids[b * U2_ + tid];
        probs_s[tid] = sel_probs[b * U2_ + tid];
        Pm[tid]  = 0.f;
        agg[tid] = 0.f;
    }
    __syncthreads();

    if (tid < U2_) atomicMin(&tbl[ids_s[tid]], tid);
    __syncthreads();

    if (tid < U2_) atomicAdd(&Pm[tbl[ids_s[tid]]], probs_s[tid]);
    __syncthreads();

    // project route mass onto union slots
    for (int v = tid; v < V_; v += 256) {
        int r = routes[b * V_ + v];
        int slot = tbl[r];
        if (slot < U2_) atomicAdd(&agg[slot], g_distr[b * V_ + v]);
    }

    // ---- per-batch epilogue terms (independent of KL scatter above) ----
    const int len = trg_lengths[b];
    float id_num = 0.f, id_den = 0.f, rate_num = 0.f, smooth = 0.f;
    float ent = 0.f, sel_num = 0.f, sel_den = 0.f;

    // id NLL + rate L1 + smoothness over t (48 items, strided)
    for (int t = tid; t < T_; t += 256) {
        float pt = 0.f, ss = 0.f;
        #pragma unroll
        for (int c = 0; c < NCHUNK; c++) {
            pt += g_ptrue4  [c * (T_ * BS_) + t * BS_ + b];
            ss += g_stepsum4[c * (T_ * BS_) + t * BS_ + b];
        }
        float m = (ss > 0.5f) ? 1.f : 0.f;
        id_num += -logf(fmaxf(pt, EPSF)) * m;
        id_den += m;
        float orv = out_rates[t * BS_ + b];
        rate_num += fabsf(orv - trg_rates[(t + 1) * BS_ + b]);
        if (t < T_ - 1 && t < len - 3)
            smooth += fabsf(out_rates[(t + 1) * BS_ + b] - orv);
    }

    // entropy over 64 probs (from smem copy)
    if (tid < U2_) {
        float p = fmaxf(probs_s[tid], EPSF);
        ent = -p * logf(p);
    }

    // selector NLL: 2 rows of K=32
    if (tid < 2) {
        float pt = 0.f, ms = 0.f;
        const float* oh = sel_onehot + (b * 2 + tid) * K_;
        const float* pp = probs_s + tid * K_;
        #pragma unroll 8
        for (int k = 0; k < K_; k++) { pt += pp[k] * oh[k]; ms += oh[k]; }
        float m = (ms > 0.5f) ? 1.f : 0.f;
        sel_num = -logf(fmaxf(pt, EPSF)) * m;
        sel_den = m;
    }

    // reduce the 7 scalar partials: warp shuffle -> smem table (deterministic)
    float vals[7] = {sel_num, sel_den, id_num, id_den, rate_num, ent, smooth};
    #pragma unroll
    for (int i = 0; i < 7; i++) {
        float v = vals[i];
        #pragma unroll
        for (int off = 16; off > 0; off >>= 1)
            v += __shfl_down_sync(0xffffffffu, v, off);
        if (lane == 0) wpart[i][warp] = v;
    }
    __syncthreads();   // also completes the agg[] scatter

    if (tid == 0) {
        float s = 0.f, PmSum = 0.f;
        int Ucnt = 0;
        #pragma unroll 4
        for (int u = 0; u < U2_; u++) {
            s += agg[u];
            PmSum += Pm[u];
            if (tbl[ids_s[u]] == u) Ucnt++;
        }
        const float invS  = 1.f / fmaxf(s, EPSF);
        const float uni   = 1.f / fmaxf((float)Ucnt, 1.f);
        const float invPm = 1.f / fmaxf(PmSum, EPSF);
        float kl = 0.f;
        for (int u = 0; u < U2_; u++) {
            if (tbl[ids_s[u]] != u) continue;      // invalid slot
            float Pb  = (s > 0.f) ? agg[u] * invS : uni;
            float Pbc = fmaxf(Pb, EPSF);
            float Pmn = fmaxf(Pm[u] * invPm, EPSF);
            kl += Pbc * (logf(Pbc) - logf(Pmn));
        }

        const int slot_map[7] = {A_SEL_NUM, A_SEL_DEN, A_ID_NUM, A_ID_DEN,
                                 A_RATE, A_ENT, A_SMOOTH};
        #pragma unroll
        for (int i = 0; i < 7; i++) {
            float v = wpart[i][0] + wpart[i][1] + wpart[i][2] + wpart[i][3] +
                      wpart[i][4] + wpart[i][5] + wpart[i][6] + wpart[i][7];
            g_part[slot_map[i] * BS_ + b] = v;
        }
        g_part[A_KL  * BS_ + b] = kl;
        g_part[A_LEN * BS_ + b] = (float)(len - 2);
    }
}

// ---------------------------------------------------------------------------
// K3: combine — one block, 256 threads: reduce 9 x 256 partials + weighting.
// ---------------------------------------------------------------------------
__global__ void __launch_bounds__(256) combine_kernel(float* __restrict__ d_out) {
    __shared__ float wsum[NACC][8];
    const int tid = threadIdx.x, lane = tid & 31, warp = tid >> 5;

    #pragma unroll
    for (int s = 0; s < NACC; s++) {
        float v = g_part[s * BS_ + tid];
        #pragma unroll
        for (int off = 16; off > 0; off >>= 1)
            v += __shfl_down_sync(0xffffffffu, v, off);
        if (lane == 0) wsum[s][warp] = v;
    }
    __syncthreads();

    if (tid == 0) {
        float acc[NACC];
        #pragma unroll
        for (int s = 0; s < NACC; s++)
            acc[s] = wsum[s][0] + wsum[s][1] + wsum[s][2] + wsum[s][3] +
                     wsum[s][4] + wsum[s][5] + wsum[s][6] + wsum[s][7];

        float loss_sel    = acc[A_SEL_NUM] / fmaxf(acc[A_SEL_DEN], 1.f);
        float loss_id     = 10.f * acc[A_ID_NUM] / fmaxf(acc[A_ID_DEN], 1.f);
        float loss_rate   = 5.f * acc[A_RATE] / fmaxf(acc[A_LEN], 1.f);
        float loss_kl     = 0.1f * acc[A_KL] / (float)BS_;
        float loss_ent    = 0.05f * 0.5f * acc[A_ENT] / (float)BS_;
        float loss_smooth = 0.5f * acc[A_SMOOTH];
        d_out[0] = loss_sel + loss_id + loss_rate + loss_kl + loss_ent + loss_smooth;
    }
}

// ---------------------------------------------------------------------------
extern "C" void kernel_launch(void* const* d_in, const int* in_sizes, int n_in,
                              void* d_out, int out_size) {
    // metadata order: selector_logits, selector_probs, selector_onehot,
    // out_ids, out_rates, trg_labels, trg_rates, trg_lengths, candi_ids, routes
    const float* sel_probs   = (const float*)d_in[1];
    const float* sel_onehot  = (const float*)d_in[2];
    const float* out_ids     = (const float*)d_in[3];
    const float* out_rates   = (const float*)d_in[4];
    const float* trg_labels  = (const float*)d_in[5];
    const float* trg_rates   = (const float*)d_in[6];
    const int*   trg_lengths = (const int*)d_in[7];
    const int*   candi_ids   = (const int*)d_in[8];
    const int*   routes      = (const int*)d_in[9];

    dim3 grid(NCHUNK, BS_);
    big_pass<<<grid, 256>>>(out_ids, trg_labels);
    kl_epi_kernel<<<BS_, 256>>>(candi_ids, sel_probs, routes, sel_onehot,
                                out_rates, trg_rates, trg_lengths);
    combine_kernel<<<1, 256>>>((float*)d_out);
}